// round 15
// baseline (speedup 1.0000x reference)
#include <cuda_runtime.h>
#include <cuda_fp16.h>
#include <math.h>

#define EPS 1e-3f

// ---------------- scratch (device globals) ----------------
__device__ __half g_X[8 * 4096 * 256];          // bn1+elu(inputs), fp16
__device__ __half g_theta[8 * 4096 * 128];      // Q, fp16
__device__ __half g_phipool[8 * 2048 * 128];    // K [b][key][ch], fp16
__device__ __half g_gT[8 * 128 * 2048];         // V transposed [b][ch][key], fp16
__device__ __half g_WT[3 * 128 * 256];          // W_theta/W_g/W_phi transposed [n][k] fp16
__device__ __half g_WzT[256 * 128];             // W_z transposed [n][k] fp16

__device__ __forceinline__ float elu_f(float v) { return v > 0.f ? v : expm1f(v); }

__device__ __forceinline__ unsigned sptr(const void* p) {
    return (unsigned)__cvta_generic_to_shared(p);
}

__device__ __forceinline__ void mma16816(float* c, const unsigned* a, unsigned b0, unsigned b1) {
    asm volatile(
        "mma.sync.aligned.m16n8k16.row.col.f32.f16.f16.f32 "
        "{%0,%1,%2,%3}, {%4,%5,%6,%7}, {%8,%9}, {%0,%1,%2,%3};"
        : "+f"(c[0]), "+f"(c[1]), "+f"(c[2]), "+f"(c[3])
        : "r"(a[0]), "r"(a[1]), "r"(a[2]), "r"(a[3]), "r"(b0), "r"(b1));
}

__device__ __forceinline__ void mma16816_h(unsigned* c, const unsigned* a, unsigned b0, unsigned b1) {
    asm volatile(
        "mma.sync.aligned.m16n8k16.row.col.f16.f16.f16.f16 "
        "{%0,%1}, {%2,%3,%4,%5}, {%6,%7}, {%0,%1};"
        : "+r"(c[0]), "+r"(c[1])
        : "r"(a[0]), "r"(a[1]), "r"(a[2]), "r"(a[3]), "r"(b0), "r"(b1));
}

__device__ __forceinline__ void ldsm4(unsigned* r, unsigned addr) {
    asm volatile("ldmatrix.sync.aligned.m8n8.x4.shared.b16 {%0,%1,%2,%3}, [%4];"
                 : "=r"(r[0]), "=r"(r[1]), "=r"(r[2]), "=r"(r[3]) : "r"(addr));
}

__device__ __forceinline__ unsigned ex2h2x(unsigned x) {
    unsigned r; asm("ex2.approx.f16x2 %0, %1;" : "=r"(r) : "r"(x)); return r;
}

// ---------------- kernel 0: weight prep (fp32 -> fp16 transposed [n][k]) ----------------
__global__ void __launch_bounds__(256) k_wprep(
    const float* __restrict__ Wth, const float* __restrict__ Wg, const float* __restrict__ Wph,
    const float* __restrict__ Wz, __half* __restrict__ WT, __half* __restrict__ WzT)
{
    int idx = blockIdx.x * 256 + threadIdx.x;   // 512*256 = 131072
    if (idx < 98304) {
        int m = idx >> 15;
        int r = idx & 32767;
        int n = r >> 8, k = r & 255;
        const float* W = (m == 0) ? Wth : (m == 1) ? Wg : Wph;
        WT[idx] = __float2half(W[k * 128 + n]);
    } else {
        int r = idx - 98304;
        int n = r >> 7, k = r & 127;
        WzT[r] = __float2half(Wz[k * 256 + n]);
    }
}

// ---------------- kernel 1: x = elu(bn1(inputs)), fp16 out ----------------
__global__ void __launch_bounds__(256) k_bn1_elu(
    const float4* __restrict__ in,
    const float* __restrict__ gamma, const float* __restrict__ beta,
    const float* __restrict__ mean, const float* __restrict__ var,
    __half* __restrict__ X)
{
    int i = blockIdx.x * 256 + threadIdx.x;
    int c = (i & 63) * 4;
    float4 v = in[i];
    float ox = elu_f(fmaf(v.x - mean[c + 0], gamma[c + 0] * rsqrtf(var[c + 0] + EPS), beta[c + 0]));
    float oy = elu_f(fmaf(v.y - mean[c + 1], gamma[c + 1] * rsqrtf(var[c + 1] + EPS), beta[c + 1]));
    float oz = elu_f(fmaf(v.z - mean[c + 2], gamma[c + 2] * rsqrtf(var[c + 2] + EPS), beta[c + 2]));
    float ow = elu_f(fmaf(v.w - mean[c + 3], gamma[c + 3] * rsqrtf(var[c + 3] + EPS), beta[c + 3]));
    __half2 h0 = __floats2half2_rn(ox, oy);
    __half2 h1 = __floats2half2_rn(oz, ow);
    uint2 u; u.x = *(unsigned*)&h0; u.y = *(unsigned*)&h1;
    *(uint2*)(X + (size_t)i * 4) = u;
}

// ---------------- kernel 2: three 1x1 convs, fp16 tensor GEMM + fused pool/transpose ----------------
#define G3_STAGE 18432   // halves per stage: As 128*72 + Ws 128*72
#define G3_SMEM (2 * G3_STAGE * 2)
__global__ void __launch_bounds__(256, 2) k_gemm3_tc(
    const __half* __restrict__ X, const __half* __restrict__ WTall,
    const float* __restrict__ b0p, const float* __restrict__ b1p, const float* __restrict__ b2p,
    __half* __restrict__ theta, __half* __restrict__ gT, __half* __restrict__ phipool)
{
    extern __shared__ __half sm[];
    const __half* WT; const float* bias;
    if (blockIdx.y == 0)      { WT = WTall;         bias = b0p; }
    else if (blockIdx.y == 1) { WT = WTall + 32768; bias = b1p; }
    else                      { WT = WTall + 65536; bias = b2p; }

    int m0 = blockIdx.x * 128;
    int tid = threadIdx.x;
    int w = tid >> 5, l = tid & 31;
    int g = l >> 2, t = l & 3;

    auto issue = [&](int stg, int kc) {
        __half* As = sm + stg * G3_STAGE;
        __half* Ws = As + 9216;
#pragma unroll
        for (int u = 0; u < 4; u++) {
            int i = tid + u * 256;
            int r = i >> 3, c8 = (i & 7) * 8;
            asm volatile("cp.async.cg.shared.global [%0], [%1], 16;\n"
                         :: "r"(sptr(As + r * 72 + c8)), "l"(X + (size_t)(m0 + r) * 256 + kc * 64 + c8));
        }
#pragma unroll
        for (int u = 0; u < 4; u++) {
            int i = tid + u * 256;
            int n = i >> 3, c8 = (i & 7) * 8;
            asm volatile("cp.async.cg.shared.global [%0], [%1], 16;\n"
                         :: "r"(sptr(Ws + n * 72 + c8)), "l"(WT + n * 256 + kc * 64 + c8));
        }
    };

    float c[16][4];
#pragma unroll
    for (int j = 0; j < 16; j++)
#pragma unroll
        for (int q = 0; q < 4; q++) c[j][q] = 0.f;

    issue(0, 0);
    asm volatile("cp.async.commit_group;\n");

    for (int kc = 0; kc < 4; ++kc) {
        int cur = kc & 1;
        asm volatile("cp.async.wait_group 0;\n");
        __syncthreads();
        if (kc < 3) {
            issue(cur ^ 1, kc + 1);
            asm volatile("cp.async.commit_group;\n");
        }
        const __half* As = sm + cur * G3_STAGE;
        const __half* Ws = As + 9216;
        int arow = w * 16 + g;
#pragma unroll
        for (int s = 0; s < 4; s++) {
            unsigned a[4];
            a[0] = *(const unsigned*)(As + arow * 72 + s * 16 + 2 * t);
            a[1] = *(const unsigned*)(As + (arow + 8) * 72 + s * 16 + 2 * t);
            a[2] = *(const unsigned*)(As + arow * 72 + s * 16 + 8 + 2 * t);
            a[3] = *(const unsigned*)(As + (arow + 8) * 72 + s * 16 + 8 + 2 * t);
#pragma unroll
            for (int j = 0; j < 16; j++) {
                unsigned bb0 = *(const unsigned*)(Ws + (8 * j + g) * 72 + s * 16 + 2 * t);
                unsigned bb1 = *(const unsigned*)(Ws + (8 * j + g) * 72 + s * 16 + 8 + 2 * t);
                mma16816(c[j], a, bb0, bb1);
            }
        }
    }

    if (blockIdx.y == 0) {
        int row = m0 + w * 16 + g;
#pragma unroll
        for (int j = 0; j < 16; j++) {
            int col = j * 8 + 2 * t;
            float bx = bias[col], by = bias[col + 1];
            *(__half2*)(theta + (size_t)row * 128 + col) = __floats2half2_rn(c[j][0] + bx, c[j][1] + by);
            *(__half2*)(theta + (size_t)(row + 8) * 128 + col) = __floats2half2_rn(c[j][2] + bx, c[j][3] + by);
        }
        return;
    }

    __syncthreads();
    __half* Cs = sm;                  // [128][136]
    int row = w * 16 + g;
#pragma unroll
    for (int j = 0; j < 16; j++) {
        int col = j * 8 + 2 * t;
        float bx = bias[col], by = bias[col + 1];
        *(__half2*)(Cs + row * 136 + col) = __floats2half2_rn(c[j][0] + bx, c[j][1] + by);
        *(__half2*)(Cs + (row + 8) * 136 + col) = __floats2half2_rn(c[j][2] + bx, c[j][3] + by);
    }
    __syncthreads();

    int bb = m0 >> 12;
    int key0 = (m0 >> 1) & 2047;

    if (blockIdx.y == 2) {
        for (int i = tid; i < 64 * 16; i += 256) {
            int r = i >> 4, c8 = (i & 15) * 8;
            uint4 a4 = *(const uint4*)(Cs + (2 * r) * 136 + c8);
            uint4 b4 = *(const uint4*)(Cs + (2 * r + 1) * 136 + c8);
            __half2* ah = (__half2*)&a4;
            __half2* bh = (__half2*)&b4;
            uint4 o;
            __half2* oh = (__half2*)&o;
#pragma unroll
            for (int k = 0; k < 4; k++) oh[k] = __hmax2(ah[k], bh[k]);
            *(uint4*)(phipool + ((size_t)bb * 2048 + key0 + r) * 128 + c8) = o;
        }
    } else {
        if (tid < 128) {
            int ch = tid;
            __half tmp[64];
#pragma unroll
            for (int k = 0; k < 64; k++)
                tmp[k] = __hmax(Cs[(2 * k) * 136 + ch], Cs[(2 * k + 1) * 136 + ch]);
            float4* dst = (float4*)(gT + ((size_t)(bb * 128 + ch)) * 2048 + key0);
            const float4* src = (const float4*)tmp;
#pragma unroll
            for (int i = 0; i < 8; i++) dst[i] = src[i];
        }
    }
}

// ---------------- kernel 3: flash attention + FUSED bn2/elu/W_z/residual epilogue ----------------
// smem layout (halves): [0, 35840) stages (-> Zs after mainloop), [35840, 70656) WzT_s [256][136],
// bytes [141312, 142336) bn2 consts (bnS[128], bnH[128]).
#define STAGE_H 17920
#define KOFF 0
#define GOFF 8704
#define WZ_OFF 35840                 // half offset of WzT_s
#define BN_BYTE 141312
#define ATTN_SMEM 142336

__device__ __forceinline__ void issue_stage(__half* sm, int stg, int kt, int tid,
                                            const __half* Kg, const __half* Gg)
{
    __half* Kd = sm + stg * STAGE_H + KOFF;
    __half* Gd = sm + stg * STAGE_H + GOFF;
    const __half* Kt = Kg + (size_t)kt * 64 * 128;
    const __half* Gt = Gg + kt * 64;
#pragma unroll
    for (int u = 0; u < 4; u++) {
        int i = tid + u * 256;
        int r = i >> 4, c8 = (i & 15) * 8;
        asm volatile("cp.async.cg.shared.global [%0], [%1], 16;\n"
                     :: "r"(sptr(Kd + r * 136 + c8)), "l"(Kt + r * 128 + c8));
    }
#pragma unroll
    for (int u = 0; u < 4; u++) {
        int i = tid + u * 256;
        int ch = i >> 3, c8 = (i & 7) * 8;
        asm volatile("cp.async.cg.shared.global [%0], [%1], 16;\n"
                     :: "r"(sptr(Gd + ch * 72 + c8)), "l"(Gt + (size_t)ch * 2048 + c8));
    }
}

__global__ void __launch_bounds__(256, 1) k_attn(
    const __half* __restrict__ theta, const __half* __restrict__ phiK,
    const __half* __restrict__ gT, const __half* __restrict__ WzT,
    const float* __restrict__ bz,
    const float* __restrict__ g2, const float* __restrict__ b2,
    const float* __restrict__ m2, const float* __restrict__ v2,
    const float* __restrict__ sita, const float* __restrict__ resid,
    float* __restrict__ out)
{
    extern __shared__ __half sm[];
    float* bnS = (float*)((char*)sm + BN_BYTE);
    float* bnH = bnS + 128;

    int b = blockIdx.y, qt = blockIdx.x;
    int tid = threadIdx.x;
    int w = tid >> 5, l = tid & 31;
    int g = l >> 2, t = l & 3;
    const float L2E = 1.4426950408889634f;
    const __half2 L2E2 = __float2half2_rn(L2E);

    int lrowB = (l & 7) + ((l >> 4) << 3);
    int lcolB = ((l >> 3) & 1) * 8;
    int lrowA = (l & 7) + (((l >> 3) & 1) << 3);
    int lcolA = (l >> 4) * 8;

    // --- prologue: bn2 consts + WzT into persistent smem; Q tile into stage region ---
    if (tid < 128) {
        float s = g2[tid] * rsqrtf(v2[tid] + EPS);
        bnS[tid] = s;
        bnH[tid] = b2[tid] - m2[tid] * s;
    }
    for (int i = tid; i < 256 * 16; i += 256) {
        int n = i >> 4, c8 = (i & 15) * 8;
        *(float4*)(sm + WZ_OFF + n * 136 + c8) = *(const float4*)(WzT + n * 128 + c8);
    }
    const __half* Qg = theta + ((size_t)b * 4096 + qt * 256) * 128;
    for (int i = tid; i < 256 * 16; i += 256) {
        int r = i >> 4, c8 = (i & 15) * 8;
        *(float4*)(sm + r * 136 + c8) = *(const float4*)(Qg + r * 128 + c8);
    }
    __syncthreads();

    unsigned a_q[2][8][4];
#pragma unroll
    for (int mt = 0; mt < 2; mt++)
#pragma unroll
        for (int s = 0; s < 8; s++)
            ldsm4(a_q[mt][s], sptr(sm + (w * 32 + mt * 16 + lrowA) * 136 + s * 16 + lcolA));
    __syncthreads();

    const __half* Kg = phiK + (size_t)b * 2048 * 128;
    const __half* Gg = gT + (size_t)b * 128 * 2048;

    unsigned oh[2][16][2];
#pragma unroll
    for (int mt = 0; mt < 2; mt++)
#pragma unroll
        for (int j = 0; j < 16; j++) { oh[mt][j][0] = 0u; oh[mt][j][1] = 0u; }
    float mreg[2][2] = {{-1e30f, -1e30f}, {-1e30f, -1e30f}};
    float lreg[2][2] = {{0.f, 0.f}, {0.f, 0.f}};

    issue_stage(sm, 0, 0, tid, Kg, Gg);
    asm volatile("cp.async.commit_group;\n");

    for (int kt = 0; kt < 32; ++kt) {
        int cur = kt & 1;
        asm volatile("cp.async.wait_group 0;\n");
        __syncthreads();
        if (kt < 31) {
            issue_stage(sm, cur ^ 1, kt + 1, tid, Kg, Gg);
            asm volatile("cp.async.commit_group;\n");
        }

        const __half* Ks = sm + cur * STAGE_H + KOFF;
        const __half* Gs = sm + cur * STAGE_H + GOFF;

        unsigned ch2[2][8][2];
#pragma unroll
        for (int mt = 0; mt < 2; mt++)
#pragma unroll
            for (int j = 0; j < 8; j++) { ch2[mt][j][0] = 0u; ch2[mt][j][1] = 0u; }
#pragma unroll
        for (int s = 0; s < 8; s++) {
#pragma unroll
            for (int jp = 0; jp < 4; jp++) {
                unsigned bm[4];
                ldsm4(bm, sptr(Ks + (16 * jp + lrowB) * 136 + s * 16 + lcolB));
#pragma unroll
                for (int mt = 0; mt < 2; mt++) {
                    mma16816_h(ch2[mt][2 * jp], a_q[mt][s], bm[0], bm[1]);
                    mma16816_h(ch2[mt][2 * jp + 1], a_q[mt][s], bm[2], bm[3]);
                }
            }
        }

        unsigned P0[2][8], P1[2][8];
        __half2 alh[2][2];
#pragma unroll
        for (int mt = 0; mt < 2; mt++) {
            __half2 hm0 = *(__half2*)&ch2[mt][0][0], hm1 = *(__half2*)&ch2[mt][0][1];
#pragma unroll
            for (int j = 1; j < 8; j++) {
                hm0 = __hmax2(hm0, *(__half2*)&ch2[mt][j][0]);
                hm1 = __hmax2(hm1, *(__half2*)&ch2[mt][j][1]);
            }
            float rmax0 = fmaxf(__low2float(hm0), __high2float(hm0));
            float rmax1 = fmaxf(__low2float(hm1), __high2float(hm1));
            rmax0 = fmaxf(rmax0, __shfl_xor_sync(0xffffffffu, rmax0, 1));
            rmax0 = fmaxf(rmax0, __shfl_xor_sync(0xffffffffu, rmax0, 2));
            rmax1 = fmaxf(rmax1, __shfl_xor_sync(0xffffffffu, rmax1, 1));
            rmax1 = fmaxf(rmax1, __shfl_xor_sync(0xffffffffu, rmax1, 2));
            float mn0 = fmaxf(mreg[mt][0], rmax0), mn1 = fmaxf(mreg[mt][1], rmax1);
            float al0 = __expf(mreg[mt][0] - mn0), al1 = __expf(mreg[mt][1] - mn1);
            mreg[mt][0] = mn0; mreg[mt][1] = mn1;
            __half2 nb0 = __float2half2_rn(-mn0 * L2E);
            __half2 nb1 = __float2half2_rn(-mn1 * L2E);

            float s0 = 0.f, s1 = 0.f;
#pragma unroll
            for (int j = 0; j < 8; j++) {
                __half2 d0 = __hfma2(*(__half2*)&ch2[mt][j][0], L2E2, nb0);
                __half2 d1 = __hfma2(*(__half2*)&ch2[mt][j][1], L2E2, nb1);
                P0[mt][j] = ex2h2x(*(unsigned*)&d0);
                P1[mt][j] = ex2h2x(*(unsigned*)&d1);
                float2 f0 = __half22float2(*(__half2*)&P0[mt][j]);
                float2 f1 = __half22float2(*(__half2*)&P1[mt][j]);
                s0 += f0.x + f0.y;
                s1 += f1.x + f1.y;
            }
            s0 += __shfl_xor_sync(0xffffffffu, s0, 1);
            s0 += __shfl_xor_sync(0xffffffffu, s0, 2);
            s1 += __shfl_xor_sync(0xffffffffu, s1, 1);
            s1 += __shfl_xor_sync(0xffffffffu, s1, 2);
            lreg[mt][0] = lreg[mt][0] * al0 + s0;
            lreg[mt][1] = lreg[mt][1] * al1 + s1;
            alh[mt][0] = __float2half2_rn(al0);
            alh[mt][1] = __float2half2_rn(al1);
        }
#pragma unroll
        for (int mt = 0; mt < 2; mt++)
#pragma unroll
            for (int j = 0; j < 16; j++) {
                *(__half2*)&oh[mt][j][0] = __hmul2(*(__half2*)&oh[mt][j][0], alh[mt][0]);
                *(__half2*)&oh[mt][j][1] = __hmul2(*(__half2*)&oh[mt][j][1], alh[mt][1]);
            }

#pragma unroll
        for (int s = 0; s < 4; s++) {
            unsigned pa[2][4];
#pragma unroll
            for (int mt = 0; mt < 2; mt++) {
                pa[mt][0] = P0[mt][2 * s]; pa[mt][1] = P1[mt][2 * s];
                pa[mt][2] = P0[mt][2 * s + 1]; pa[mt][3] = P1[mt][2 * s + 1];
            }
#pragma unroll
            for (int jp = 0; jp < 8; jp++) {
                unsigned gm[4];
                ldsm4(gm, sptr(Gs + (16 * jp + lrowB) * 72 + s * 16 + lcolB));
#pragma unroll
                for (int mt = 0; mt < 2; mt++) {
                    mma16816_h(oh[mt][2 * jp], pa[mt], gm[0], gm[1]);
                    mma16816_h(oh[mt][2 * jp + 1], pa[mt], gm[2], gm[3]);
                }
            }
        }
    }

    // ---- fused epilogue: Z = elu(bn2(O/l)) -> smem; out = Z @ WzT^T * sita + resid ----
    __syncthreads();                // all warps done with stage K/G
    __half* Zs = sm;                // [256][136]
#pragma unroll
    for (int mt = 0; mt < 2; mt++) {
        float inv0 = 1.f / lreg[mt][0], inv1 = 1.f / lreg[mt][1];
        int r0 = w * 32 + mt * 16 + g;
#pragma unroll
        for (int j = 0; j < 16; j++) {
            int c0 = j * 8 + 2 * t;
            float2 lo = __half22float2(*(__half2*)&oh[mt][j][0]);
            float2 hi = __half22float2(*(__half2*)&oh[mt][j][1]);
            float z0 = elu_f(fmaf(lo.x * inv0, bnS[c0], bnH[c0]));
            float z1 = elu_f(fmaf(lo.y * inv0, bnS[c0 + 1], bnH[c0 + 1]));
            float z2 = elu_f(fmaf(hi.x * inv1, bnS[c0], bnH[c0]));
            float z3 = elu_f(fmaf(hi.y * inv1, bnS[c0 + 1], bnH[c0 + 1]));
            *(__half2*)(Zs + r0 * 136 + c0) = __floats2half2_rn(z0, z1);
            *(__half2*)(Zs + (r0 + 8) * 136 + c0) = __floats2half2_rn(z2, z3);
        }
    }
    __syncthreads();

    float st = *sita;
    size_t grow0 = (size_t)b * 4096 + qt * 256 + w * 32;
    const __half* Wzs = sm + WZ_OFF;

#pragma unroll
    for (int nc = 0; nc < 2; nc++) {
#pragma unroll
        for (int mt = 0; mt < 2; mt++) {
            float c[16][4];
#pragma unroll
            for (int j = 0; j < 16; j++)
#pragma unroll
                for (int q = 0; q < 4; q++) c[j][q] = 0.f;
#pragma unroll
            for (int s = 0; s < 8; s++) {
                unsigned a[4];
                ldsm4(a, sptr(Zs + (w * 32 + mt * 16 + lrowA) * 136 + s * 16 + lcolA));
#pragma unroll
                for (int jp = 0; jp < 8; jp++) {
                    unsigned bm[4];
                    ldsm4(bm, sptr(Wzs + (nc * 128 + 16 * jp + lrowB) * 136 + s * 16 + lcolB));
                    mma16816(c[2 * jp], a, bm[0], bm[1]);
                    mma16816(c[2 * jp + 1], a, bm[2], bm[3]);
                }
            }
            size_t r0 = grow0 + mt * 16 + g;
#pragma unroll
            for (int j = 0; j < 16; j++) {
                int col = nc * 128 + j * 8 + 2 * t;
                float bx = bz[col], by = bz[col + 1];
                float2 rv0 = *(const float2*)(resid + r0 * 256 + col);
                float2 rv1 = *(const float2*)(resid + (r0 + 8) * 256 + col);
                float2 v0 = make_float2(fmaf(c[j][0] + bx, st, rv0.x), fmaf(c[j][1] + by, st, rv0.y));
                float2 v1 = make_float2(fmaf(c[j][2] + bx, st, rv1.x), fmaf(c[j][3] + by, st, rv1.y));
                *(float2*)(out + r0 * 256 + col) = v0;
                *(float2*)(out + (r0 + 8) * 256 + col) = v1;
            }
        }
    }
}

// ---------------- launcher ----------------
extern "C" void kernel_launch(void* const* d_in, const int* in_sizes, int n_in,
                              void* d_out, int out_size)
{
    const float* inputs = (const float*)d_in[0];
    const float* bn1g = (const float*)d_in[1];
    const float* bn1b = (const float*)d_in[2];
    const float* bn1m = (const float*)d_in[3];
    const float* bn1v = (const float*)d_in[4];
    const float* bn2g = (const float*)d_in[5];
    const float* bn2b = (const float*)d_in[6];
    const float* bn2m = (const float*)d_in[7];
    const float* bn2v = (const float*)d_in[8];
    const float* Wg   = (const float*)d_in[9];
    const float* bg   = (const float*)d_in[10];
    const float* Wth  = (const float*)d_in[11];
    const float* bth  = (const float*)d_in[12];
    const float* Wph  = (const float*)d_in[13];
    const float* bph  = (const float*)d_in[14];
    const float* Wz   = (const float*)d_in[15];
    const float* bz   = (const float*)d_in[16];
    const float* sita = (const float*)d_in[17];
    float* out = (float*)d_out;

    __half *X, *theta, *phipool, *gT, *WT, *WzT;
    cudaGetSymbolAddress((void**)&X, g_X);
    cudaGetSymbolAddress((void**)&theta, g_theta);
    cudaGetSymbolAddress((void**)&phipool, g_phipool);
    cudaGetSymbolAddress((void**)&gT, g_gT);
    cudaGetSymbolAddress((void**)&WT, g_WT);
    cudaGetSymbolAddress((void**)&WzT, g_WzT);

    cudaFuncSetAttribute(k_attn, cudaFuncAttributeMaxDynamicSharedMemorySize, ATTN_SMEM);
    cudaFuncSetAttribute(k_gemm3_tc, cudaFuncAttributeMaxDynamicSharedMemorySize, G3_SMEM);

    // 0) weight prep
    k_wprep<<<512, 256>>>(Wth, Wg, Wph, Wz, WT, WzT);
    // 1) bn1 + elu (fp16 out)
    k_bn1_elu<<<8192, 256>>>((const float4*)inputs, bn1g, bn1b, bn1m, bn1v, X);
    // 2) theta / g / phi convs (tensor core) with fused pool+transpose for g/phi
    k_gemm3_tc<<<dim3(256, 3), 256, G3_SMEM>>>(X, WT, bth, bg, bph, theta, gT, phipool);
    // 3) flash attention + fused bn2/elu/W_z/residual epilogue
    k_attn<<<dim3(16, 8), 256, ATTN_SMEM>>>(theta, phipool, gT, WzT, bz,
                                            bn2g, bn2b, bn2m, bn2v, sita, inputs, out);
}

// round 16
// speedup vs baseline: 1.5075x; 1.5075x over previous
#include <cuda_runtime.h>
#include <cuda_fp16.h>
#include <math.h>

#define EPS 1e-3f

// ---------------- scratch (device globals) ----------------
__device__ __half g_X[8 * 4096 * 256];          // bn1+elu(inputs), fp16
__device__ __half g_theta[8 * 4096 * 128];      // Q, fp16
__device__ __half g_phipool[8 * 2048 * 128];    // K [b][key][ch], fp16
__device__ __half g_gT[8 * 128 * 2048];         // V transposed [b][ch][key], fp16
__device__ __half g_Y[8 * 4096 * 128];          // attention out, fp16
__device__ __half g_WT[3 * 128 * 256];          // W_theta/W_g/W_phi transposed [n][k] fp16
__device__ __half g_WzT[256 * 128];             // W_z transposed [n][k] fp16

__device__ __forceinline__ float elu_f(float v) { return v > 0.f ? v : expm1f(v); }

__device__ __forceinline__ unsigned sptr(const void* p) {
    return (unsigned)__cvta_generic_to_shared(p);
}

__device__ __forceinline__ void mma16816(float* c, const unsigned* a, unsigned b0, unsigned b1) {
    asm volatile(
        "mma.sync.aligned.m16n8k16.row.col.f32.f16.f16.f32 "
        "{%0,%1,%2,%3}, {%4,%5,%6,%7}, {%8,%9}, {%0,%1,%2,%3};"
        : "+f"(c[0]), "+f"(c[1]), "+f"(c[2]), "+f"(c[3])
        : "r"(a[0]), "r"(a[1]), "r"(a[2]), "r"(a[3]), "r"(b0), "r"(b1));
}

__device__ __forceinline__ void mma16816_h(unsigned* c, const unsigned* a, unsigned b0, unsigned b1) {
    asm volatile(
        "mma.sync.aligned.m16n8k16.row.col.f16.f16.f16.f16 "
        "{%0,%1}, {%2,%3,%4,%5}, {%6,%7}, {%0,%1};"
        : "+r"(c[0]), "+r"(c[1])
        : "r"(a[0]), "r"(a[1]), "r"(a[2]), "r"(a[3]), "r"(b0), "r"(b1));
}

__device__ __forceinline__ void ldsm4(unsigned* r, unsigned addr) {
    asm volatile("ldmatrix.sync.aligned.m8n8.x4.shared.b16 {%0,%1,%2,%3}, [%4];"
                 : "=r"(r[0]), "=r"(r[1]), "=r"(r[2]), "=r"(r[3]) : "r"(addr));
}

__device__ __forceinline__ unsigned ex2h2x(unsigned x) {
    unsigned r; asm("ex2.approx.f16x2 %0, %1;" : "=r"(r) : "r"(x)); return r;
}

// ---------------- kernel 1: bn1+elu (blocks < 8192) fused with weight prep (blocks >= 8192) ----------------
__global__ void __launch_bounds__(256) k_bn1_wprep(
    const float4* __restrict__ in,
    const float* __restrict__ gamma, const float* __restrict__ beta,
    const float* __restrict__ mean, const float* __restrict__ var,
    __half* __restrict__ X,
    const float* __restrict__ Wth, const float* __restrict__ Wg, const float* __restrict__ Wph,
    const float* __restrict__ Wz, __half* __restrict__ WT, __half* __restrict__ WzT)
{
    if (blockIdx.x >= 8192) {
        int idx = (blockIdx.x - 8192) * 256 + threadIdx.x;   // 512*256 = 131072
        if (idx < 98304) {
            int m = idx >> 15;
            int r = idx & 32767;
            int n = r >> 8, k = r & 255;
            const float* W = (m == 0) ? Wth : (m == 1) ? Wg : Wph;
            WT[idx] = __float2half(W[k * 128 + n]);
        } else {
            int r = idx - 98304;
            int n = r >> 7, k = r & 127;
            WzT[r] = __float2half(Wz[k * 256 + n]);
        }
        return;
    }
    int i = blockIdx.x * 256 + threadIdx.x;
    int c = (i & 63) * 4;
    float4 v = in[i];
    float ox = elu_f(fmaf(v.x - mean[c + 0], gamma[c + 0] * rsqrtf(var[c + 0] + EPS), beta[c + 0]));
    float oy = elu_f(fmaf(v.y - mean[c + 1], gamma[c + 1] * rsqrtf(var[c + 1] + EPS), beta[c + 1]));
    float oz = elu_f(fmaf(v.z - mean[c + 2], gamma[c + 2] * rsqrtf(var[c + 2] + EPS), beta[c + 2]));
    float ow = elu_f(fmaf(v.w - mean[c + 3], gamma[c + 3] * rsqrtf(var[c + 3] + EPS), beta[c + 3]));
    __half2 h0 = __floats2half2_rn(ox, oy);
    __half2 h1 = __floats2half2_rn(oz, ow);
    uint2 u; u.x = *(unsigned*)&h0; u.y = *(unsigned*)&h1;
    *(uint2*)(X + (size_t)i * 4) = u;
}

// ---------------- kernel 2: three 1x1 convs, fp16 tensor GEMM + fused pool/transpose ----------------
#define G3_STAGE 18432   // halves per stage: As 128*72 + Ws 128*72
#define G3_SMEM (2 * G3_STAGE * 2)
__global__ void __launch_bounds__(256, 2) k_gemm3_tc(
    const __half* __restrict__ X, const __half* __restrict__ WTall,
    const float* __restrict__ b0p, const float* __restrict__ b1p, const float* __restrict__ b2p,
    __half* __restrict__ theta, __half* __restrict__ gT, __half* __restrict__ phipool)
{
    extern __shared__ __half sm[];
    const __half* WT; const float* bias;
    if (blockIdx.y == 0)      { WT = WTall;         bias = b0p; }
    else if (blockIdx.y == 1) { WT = WTall + 32768; bias = b1p; }
    else                      { WT = WTall + 65536; bias = b2p; }

    int m0 = blockIdx.x * 128;
    int tid = threadIdx.x;
    int w = tid >> 5, l = tid & 31;
    int g = l >> 2, t = l & 3;

    auto issue = [&](int stg, int kc) {
        __half* As = sm + stg * G3_STAGE;
        __half* Ws = As + 9216;
#pragma unroll
        for (int u = 0; u < 4; u++) {
            int i = tid + u * 256;
            int r = i >> 3, c8 = (i & 7) * 8;
            asm volatile("cp.async.cg.shared.global [%0], [%1], 16;\n"
                         :: "r"(sptr(As + r * 72 + c8)), "l"(X + (size_t)(m0 + r) * 256 + kc * 64 + c8));
        }
#pragma unroll
        for (int u = 0; u < 4; u++) {
            int i = tid + u * 256;
            int n = i >> 3, c8 = (i & 7) * 8;
            asm volatile("cp.async.cg.shared.global [%0], [%1], 16;\n"
                         :: "r"(sptr(Ws + n * 72 + c8)), "l"(WT + n * 256 + kc * 64 + c8));
        }
    };

    float c[16][4];
#pragma unroll
    for (int j = 0; j < 16; j++)
#pragma unroll
        for (int q = 0; q < 4; q++) c[j][q] = 0.f;

    issue(0, 0);
    asm volatile("cp.async.commit_group;\n");

    for (int kc = 0; kc < 4; ++kc) {
        int cur = kc & 1;
        asm volatile("cp.async.wait_group 0;\n");
        __syncthreads();
        if (kc < 3) {
            issue(cur ^ 1, kc + 1);
            asm volatile("cp.async.commit_group;\n");
        }
        const __half* As = sm + cur * G3_STAGE;
        const __half* Ws = As + 9216;
        int arow = w * 16 + g;
#pragma unroll
        for (int s = 0; s < 4; s++) {
            unsigned a[4];
            a[0] = *(const unsigned*)(As + arow * 72 + s * 16 + 2 * t);
            a[1] = *(const unsigned*)(As + (arow + 8) * 72 + s * 16 + 2 * t);
            a[2] = *(const unsigned*)(As + arow * 72 + s * 16 + 8 + 2 * t);
            a[3] = *(const unsigned*)(As + (arow + 8) * 72 + s * 16 + 8 + 2 * t);
#pragma unroll
            for (int j = 0; j < 16; j++) {
                unsigned bb0 = *(const unsigned*)(Ws + (8 * j + g) * 72 + s * 16 + 2 * t);
                unsigned bb1 = *(const unsigned*)(Ws + (8 * j + g) * 72 + s * 16 + 8 + 2 * t);
                mma16816(c[j], a, bb0, bb1);
            }
        }
    }

    if (blockIdx.y == 0) {
        int row = m0 + w * 16 + g;
#pragma unroll
        for (int j = 0; j < 16; j++) {
            int col = j * 8 + 2 * t;
            float bx = bias[col], by = bias[col + 1];
            *(__half2*)(theta + (size_t)row * 128 + col) = __floats2half2_rn(c[j][0] + bx, c[j][1] + by);
            *(__half2*)(theta + (size_t)(row + 8) * 128 + col) = __floats2half2_rn(c[j][2] + bx, c[j][3] + by);
        }
        return;
    }

    __syncthreads();
    __half* Cs = sm;                  // [128][136]
    int row = w * 16 + g;
#pragma unroll
    for (int j = 0; j < 16; j++) {
        int col = j * 8 + 2 * t;
        float bx = bias[col], by = bias[col + 1];
        *(__half2*)(Cs + row * 136 + col) = __floats2half2_rn(c[j][0] + bx, c[j][1] + by);
        *(__half2*)(Cs + (row + 8) * 136 + col) = __floats2half2_rn(c[j][2] + bx, c[j][3] + by);
    }
    __syncthreads();

    int bb = m0 >> 12;
    int key0 = (m0 >> 1) & 2047;

    if (blockIdx.y == 2) {
        for (int i = tid; i < 64 * 16; i += 256) {
            int r = i >> 4, c8 = (i & 15) * 8;
            uint4 a4 = *(const uint4*)(Cs + (2 * r) * 136 + c8);
            uint4 b4 = *(const uint4*)(Cs + (2 * r + 1) * 136 + c8);
            __half2* ah = (__half2*)&a4;
            __half2* bh = (__half2*)&b4;
            uint4 o;
            __half2* oh = (__half2*)&o;
#pragma unroll
            for (int k = 0; k < 4; k++) oh[k] = __hmax2(ah[k], bh[k]);
            *(uint4*)(phipool + ((size_t)bb * 2048 + key0 + r) * 128 + c8) = o;
        }
    } else {
        if (tid < 128) {
            int ch = tid;
            __half tmp[64];
#pragma unroll
            for (int k = 0; k < 64; k++)
                tmp[k] = __hmax(Cs[(2 * k) * 136 + ch], Cs[(2 * k + 1) * 136 + ch]);
            float4* dst = (float4*)(gT + ((size_t)(bb * 128 + ch)) * 2048 + key0);
            const float4* src = (const float4*)tmp;
#pragma unroll
            for (int i = 0; i < 8; i++) dst[i] = src[i];
        }
    }
}

// ---------------- kernel 3: flash attention — R14-exact + __any_sync rescale guard ----------------
#define STAGE_H 17920
#define KOFF 0
#define GOFF 8704
#define ATTN_SMEM (2 * STAGE_H * 2)

__device__ __forceinline__ void issue_stage(__half* sm, int stg, int kt, int tid,
                                            const __half* Kg, const __half* Gg)
{
    __half* Kd = sm + stg * STAGE_H + KOFF;
    __half* Gd = sm + stg * STAGE_H + GOFF;
    const __half* Kt = Kg + (size_t)kt * 64 * 128;
    const __half* Gt = Gg + kt * 64;
#pragma unroll
    for (int u = 0; u < 4; u++) {
        int i = tid + u * 256;
        int r = i >> 4, c8 = (i & 15) * 8;
        asm volatile("cp.async.cg.shared.global [%0], [%1], 16;\n"
                     :: "r"(sptr(Kd + r * 136 + c8)), "l"(Kt + r * 128 + c8));
    }
#pragma unroll
    for (int u = 0; u < 4; u++) {
        int i = tid + u * 256;
        int ch = i >> 3, c8 = (i & 7) * 8;
        asm volatile("cp.async.cg.shared.global [%0], [%1], 16;\n"
                     :: "r"(sptr(Gd + ch * 72 + c8)), "l"(Gt + (size_t)ch * 2048 + c8));
    }
}

__global__ void __launch_bounds__(256, 1) k_attn(
    const __half* __restrict__ theta, const __half* __restrict__ phiK,
    const __half* __restrict__ gT, __half* __restrict__ Y)
{
    extern __shared__ __half sm[];

    int b = blockIdx.y, qt = blockIdx.x;
    int tid = threadIdx.x;
    int w = tid >> 5, l = tid & 31;
    int g = l >> 2, t = l & 3;
    const float L2E = 1.4426950408889634f;
    const __half2 L2E2 = __float2half2_rn(L2E);

    int lrowB = (l & 7) + ((l >> 4) << 3);
    int lcolB = ((l >> 3) & 1) * 8;
    int lrowA = (l & 7) + (((l >> 3) & 1) << 3);
    int lcolA = (l >> 4) * 8;

    const __half* Qg = theta + ((size_t)b * 4096 + qt * 256) * 128;
    for (int i = tid; i < 256 * 16; i += 256) {
        int r = i >> 4, c8 = (i & 15) * 8;
        *(float4*)(sm + r * 136 + c8) = *(const float4*)(Qg + r * 128 + c8);
    }
    __syncthreads();

    unsigned a_q[2][8][4];
#pragma unroll
    for (int mt = 0; mt < 2; mt++)
#pragma unroll
        for (int s = 0; s < 8; s++)
            ldsm4(a_q[mt][s], sptr(sm + (w * 32 + mt * 16 + lrowA) * 136 + s * 16 + lcolA));
    __syncthreads();

    const __half* Kg = phiK + (size_t)b * 2048 * 128;
    const __half* Gg = gT + (size_t)b * 128 * 2048;

    unsigned oh[2][16][2];
#pragma unroll
    for (int mt = 0; mt < 2; mt++)
#pragma unroll
        for (int j = 0; j < 16; j++) { oh[mt][j][0] = 0u; oh[mt][j][1] = 0u; }
    float mreg[2][2] = {{-1e30f, -1e30f}, {-1e30f, -1e30f}};
    float lreg[2][2] = {{0.f, 0.f}, {0.f, 0.f}};

    issue_stage(sm, 0, 0, tid, Kg, Gg);
    asm volatile("cp.async.commit_group;\n");

    for (int kt = 0; kt < 32; ++kt) {
        int cur = kt & 1;
        asm volatile("cp.async.wait_group 0;\n");
        __syncthreads();
        if (kt < 31) {
            issue_stage(sm, cur ^ 1, kt + 1, tid, Kg, Gg);
            asm volatile("cp.async.commit_group;\n");
        }

        const __half* Ks = sm + cur * STAGE_H + KOFF;
        const __half* Gs = sm + cur * STAGE_H + GOFF;

        unsigned ch2[2][8][2];
#pragma unroll
        for (int mt = 0; mt < 2; mt++)
#pragma unroll
            for (int j = 0; j < 8; j++) { ch2[mt][j][0] = 0u; ch2[mt][j][1] = 0u; }
#pragma unroll
        for (int s = 0; s < 8; s++) {
#pragma unroll
            for (int jp = 0; jp < 4; jp++) {
                unsigned bm[4];
                ldsm4(bm, sptr(Ks + (16 * jp + lrowB) * 136 + s * 16 + lcolB));
#pragma unroll
                for (int mt = 0; mt < 2; mt++) {
                    mma16816_h(ch2[mt][2 * jp], a_q[mt][s], bm[0], bm[1]);
                    mma16816_h(ch2[mt][2 * jp + 1], a_q[mt][s], bm[2], bm[3]);
                }
            }
        }

        unsigned P0[2][8], P1[2][8];
        __half2 alh[2][2];
        float alf[2][2];
#pragma unroll
        for (int mt = 0; mt < 2; mt++) {
            __half2 hm0 = *(__half2*)&ch2[mt][0][0], hm1 = *(__half2*)&ch2[mt][0][1];
#pragma unroll
            for (int j = 1; j < 8; j++) {
                hm0 = __hmax2(hm0, *(__half2*)&ch2[mt][j][0]);
                hm1 = __hmax2(hm1, *(__half2*)&ch2[mt][j][1]);
            }
            float rmax0 = fmaxf(__low2float(hm0), __high2float(hm0));
            float rmax1 = fmaxf(__low2float(hm1), __high2float(hm1));
            rmax0 = fmaxf(rmax0, __shfl_xor_sync(0xffffffffu, rmax0, 1));
            rmax0 = fmaxf(rmax0, __shfl_xor_sync(0xffffffffu, rmax0, 2));
            rmax1 = fmaxf(rmax1, __shfl_xor_sync(0xffffffffu, rmax1, 1));
            rmax1 = fmaxf(rmax1, __shfl_xor_sync(0xffffffffu, rmax1, 2));
            float mn0 = fmaxf(mreg[mt][0], rmax0), mn1 = fmaxf(mreg[mt][1], rmax1);
            float al0 = __expf(mreg[mt][0] - mn0), al1 = __expf(mreg[mt][1] - mn1);
            mreg[mt][0] = mn0; mreg[mt][1] = mn1;
            __half2 nb0 = __float2half2_rn(-mn0 * L2E);
            __half2 nb1 = __float2half2_rn(-mn1 * L2E);

            float s0 = 0.f, s1 = 0.f;
#pragma unroll
            for (int j = 0; j < 8; j++) {
                __half2 d0 = __hfma2(*(__half2*)&ch2[mt][j][0], L2E2, nb0);
                __half2 d1 = __hfma2(*(__half2*)&ch2[mt][j][1], L2E2, nb1);
                P0[mt][j] = ex2h2x(*(unsigned*)&d0);
                P1[mt][j] = ex2h2x(*(unsigned*)&d1);
                float2 f0 = __half22float2(*(__half2*)&P0[mt][j]);
                float2 f1 = __half22float2(*(__half2*)&P1[mt][j]);
                s0 += f0.x + f0.y;
                s1 += f1.x + f1.y;
            }
            s0 += __shfl_xor_sync(0xffffffffu, s0, 1);
            s0 += __shfl_xor_sync(0xffffffffu, s0, 2);
            s1 += __shfl_xor_sync(0xffffffffu, s1, 1);
            s1 += __shfl_xor_sync(0xffffffffu, s1, 2);
            lreg[mt][0] = lreg[mt][0] * al0 + s0;
            lreg[mt][1] = lreg[mt][1] * al1 + s1;
            alh[mt][0] = __float2half2_rn(al0);
            alh[mt][1] = __float2half2_rn(al1);
            alf[mt][0] = al0; alf[mt][1] = al1;
        }

        bool need = (alf[0][0] != 1.f) | (alf[0][1] != 1.f) |
                    (alf[1][0] != 1.f) | (alf[1][1] != 1.f);
        if (__any_sync(0xffffffffu, need)) {
#pragma unroll
            for (int mt = 0; mt < 2; mt++)
#pragma unroll
                for (int j = 0; j < 16; j++) {
                    *(__half2*)&oh[mt][j][0] = __hmul2(*(__half2*)&oh[mt][j][0], alh[mt][0]);
                    *(__half2*)&oh[mt][j][1] = __hmul2(*(__half2*)&oh[mt][j][1], alh[mt][1]);
                }
        }

#pragma unroll
        for (int s = 0; s < 4; s++) {
            unsigned pa[2][4];
#pragma unroll
            for (int mt = 0; mt < 2; mt++) {
                pa[mt][0] = P0[mt][2 * s]; pa[mt][1] = P1[mt][2 * s];
                pa[mt][2] = P0[mt][2 * s + 1]; pa[mt][3] = P1[mt][2 * s + 1];
            }
#pragma unroll
            for (int jp = 0; jp < 8; jp++) {
                unsigned gm[4];
                ldsm4(gm, sptr(Gs + (16 * jp + lrowB) * 72 + s * 16 + lcolB));
#pragma unroll
                for (int mt = 0; mt < 2; mt++) {
                    mma16816_h(oh[mt][2 * jp], pa[mt], gm[0], gm[1]);
                    mma16816_h(oh[mt][2 * jp + 1], pa[mt], gm[2], gm[3]);
                }
            }
        }
    }

#pragma unroll
    for (int mt = 0; mt < 2; mt++) {
        float inv0 = 1.f / lreg[mt][0], inv1 = 1.f / lreg[mt][1];
        __half2 i0 = __float2half2_rn(inv0), i1 = __float2half2_rn(inv1);
        size_t base = (size_t)b * 4096 + qt * 256 + w * 32 + mt * 16;
#pragma unroll
        for (int j = 0; j < 16; j++) {
            __half2 v0 = __hmul2(*(__half2*)&oh[mt][j][0], i0);
            __half2 v1 = __hmul2(*(__half2*)&oh[mt][j][1], i1);
            *(__half2*)(Y + (base + g) * 128 + j * 8 + 2 * t) = v0;
            *(__half2*)(Y + (base + g + 8) * 128 + j * 8 + 2 * t) = v1;
        }
    }
}

// ---------------- kernel 4: out = elu(bn2(Y)) @ W_z + b_z, *sita + inputs ----------------
// Both n-halves per CTA (Y read once); fp32 smem staging -> coalesced float4 epilogue.
// smem: bn consts 1KB + As[128][136] fp16 (34.8KB) + Ws[256][136] fp16 (69.6KB) = ~105.5KB.
#define GZ_SMEM (1024 + 128 * 136 * 2 + 256 * 136 * 2)
__global__ void __launch_bounds__(256, 1) k_gemm_z_tc(
    const __half* __restrict__ Yh, const __half* __restrict__ WzT,
    const float* __restrict__ bz,
    const float* __restrict__ g2, const float* __restrict__ b2,
    const float* __restrict__ m2, const float* __restrict__ v2,
    const float* __restrict__ sita, const float* __restrict__ resid, float* __restrict__ out)
{
    extern __shared__ char smz[];
    float* bnS = (float*)smz;
    float* bnH = bnS + 128;
    __half* As = (__half*)(bnH + 128);          // [128][136]
    __half* Ws = As + 128 * 136;                // [256][136]
    float* Cs = (float*)As;                     // fp32 staging [128][132] (reuses As after mma of each half? no — As needed for both halves; stage into Ws region instead)
    float* CsW = (float*)Ws;                    // staging overlaps Ws after both mma sweeps

    int m0 = blockIdx.x * 128;
    int tid = threadIdx.x;
    int w = tid >> 5, l = tid & 31;
    int g = l >> 2, t = l & 3;

    if (tid < 128) {
        float s = g2[tid] * rsqrtf(v2[tid] + EPS);
        bnS[tid] = s;
        bnH[tid] = b2[tid] - m2[tid] * s;
    }
    __syncthreads();

    // A fill: elu(bn2(Y)) once for both n-halves
    for (int i = tid; i < 128 * 16; i += 256) {
        int r = i >> 4, c8 = (i & 15) * 8;
        uint4 u = *(const uint4*)(Yh + (size_t)(m0 + r) * 128 + c8);
        __half2* hp = (__half2*)&u;
        uint4 o;
        __half2* op = (__half2*)&o;
#pragma unroll
        for (int k = 0; k < 4; k++) {
            float2 f = __half22float2(hp[k]);
            int c = c8 + 2 * k;
            f.x = elu_f(fmaf(f.x, bnS[c], bnH[c]));
            f.y = elu_f(fmaf(f.y, bnS[c + 1], bnH[c + 1]));
            op[k] = __floats2half2_rn(f.x, f.y);
        }
        *(uint4*)(As + r * 136 + c8) = o;
    }
    // W fill: all 256 n-rows
    for (int i = tid; i < 256 * 16; i += 256) {
        int n = i >> 4, c8 = (i & 15) * 8;
        *(uint4*)(Ws + n * 136 + c8) = *(const uint4*)(WzT + (size_t)n * 128 + c8);
    }
    __syncthreads();

    int arow = w * 16 + g;
    float st = *sita;

    // accumulate both halves, keeping 64 accums live at a time
#pragma unroll
    for (int nc = 0; nc < 2; nc++) {
        float c[16][4];
#pragma unroll
        for (int j = 0; j < 16; j++)
#pragma unroll
            for (int q = 0; q < 4; q++) c[j][q] = 0.f;

#pragma unroll
        for (int s = 0; s < 8; s++) {
            unsigned a[4];
            a[0] = *(const unsigned*)(As + arow * 136 + s * 16 + 2 * t);
            a[1] = *(const unsigned*)(As + (arow + 8) * 136 + s * 16 + 2 * t);
            a[2] = *(const unsigned*)(As + arow * 136 + s * 16 + 8 + 2 * t);
            a[3] = *(const unsigned*)(As + (arow + 8) * 136 + s * 16 + 8 + 2 * t);
#pragma unroll
            for (int j = 0; j < 16; j++) {
                unsigned bb0 = *(const unsigned*)(Ws + (nc * 128 + 8 * j + g) * 136 + s * 16 + 2 * t);
                unsigned bb1 = *(const unsigned*)(Ws + (nc * 128 + 8 * j + g) * 136 + s * 16 + 8 + 2 * t);
                mma16816(c[j], a, bb0, bb1);
            }
        }

        // direct epilogue (float2, as R9) — keeps As/Ws intact for second half
        size_t row = (size_t)(m0 + arow);
#pragma unroll
        for (int j = 0; j < 16; j++) {
            int col = nc * 128 + j * 8 + 2 * t;
            float bx = bz[col], by = bz[col + 1];
            float2 r0 = *(const float2*)(resid + row * 256 + col);
            float2 r1 = *(const float2*)(resid + (row + 8) * 256 + col);
            float2 v0 = make_float2(fmaf(c[j][0] + bx, st, r0.x), fmaf(c[j][1] + by, st, r0.y));
            float2 v1 = make_float2(fmaf(c[j][2] + bx, st, r1.x), fmaf(c[j][3] + by, st, r1.y));
            *(float2*)(out + row * 256 + col) = v0;
            *(float2*)(out + (row + 8) * 256 + col) = v1;
        }
    }
    (void)Cs; (void)CsW;
}

// ---------------- launcher ----------------
extern "C" void kernel_launch(void* const* d_in, const int* in_sizes, int n_in,
                              void* d_out, int out_size)
{
    const float* inputs = (const float*)d_in[0];
    const float* bn1g = (const float*)d_in[1];
    const float* bn1b = (const float*)d_in[2];
    const float* bn1m = (const float*)d_in[3];
    const float* bn1v = (const float*)d_in[4];
    const float* bn2g = (const float*)d_in[5];
    const float* bn2b = (const float*)d_in[6];
    const float* bn2m = (const float*)d_in[7];
    const float* bn2v = (const float*)d_in[8];
    const float* Wg   = (const float*)d_in[9];
    const float* bg   = (const float*)d_in[10];
    const float* Wth  = (const float*)d_in[11];
    const float* bth  = (const float*)d_in[12];
    const float* Wph  = (const float*)d_in[13];
    const float* bph  = (const float*)d_in[14];
    const float* Wz   = (const float*)d_in[15];
    const float* bz   = (const float*)d_in[16];
    const float* sita = (const float*)d_in[17];
    float* out = (float*)d_out;

    __half *X, *theta, *phipool, *gT, *Y, *WT, *WzT;
    cudaGetSymbolAddress((void**)&X, g_X);
    cudaGetSymbolAddress((void**)&theta, g_theta);
    cudaGetSymbolAddress((void**)&phipool, g_phipool);
    cudaGetSymbolAddress((void**)&gT, g_gT);
    cudaGetSymbolAddress((void**)&Y, g_Y);
    cudaGetSymbolAddress((void**)&WT, g_WT);
    cudaGetSymbolAddress((void**)&WzT, g_WzT);

    cudaFuncSetAttribute(k_attn, cudaFuncAttributeMaxDynamicSharedMemorySize, ATTN_SMEM);
    cudaFuncSetAttribute(k_gemm3_tc, cudaFuncAttributeMaxDynamicSharedMemorySize, G3_SMEM);
    cudaFuncSetAttribute(k_gemm_z_tc, cudaFuncAttributeMaxDynamicSharedMemorySize, GZ_SMEM);

    // 1) bn1 + elu (fp16 out) fused with weight prep
    k_bn1_wprep<<<8704, 256>>>((const float4*)inputs, bn1g, bn1b, bn1m, bn1v, X,
                               Wth, Wg, Wph, Wz, WT, WzT);
    // 2) theta / g / phi convs (tensor core) with fused pool+transpose for g/phi
    k_gemm3_tc<<<dim3(256, 3), 256, G3_SMEM>>>(X, WT, bth, bg, bph, theta, gT, phipool);
    // 3) flash attention (8 warps x 32 rows, Q tile 256, 2-stage, guarded rescale)
    k_attn<<<dim3(16, 8), 256, ATTN_SMEM>>>(theta, phipool, gT, Y);
    // 4) bn2+elu -> W_z -> *sita + residual (both n-halves per CTA)
    k_gemm_z_tc<<<256, 256, GZ_SMEM>>>(Y, WzT, bz, bn2g, bn2b, bn2m, bn2v, sita, inputs, out);
}

// round 17
// speedup vs baseline: 1.6126x; 1.0697x over previous
#include <cuda_runtime.h>
#include <cuda_fp16.h>
#include <math.h>

#define EPS 1e-3f

// ---------------- scratch (device globals) ----------------
__device__ __half g_X[8 * 4096 * 256];          // bn1+elu(inputs), fp16
__device__ __half g_theta[8 * 4096 * 128];      // Q, fp16
__device__ __half g_phipool[8 * 2048 * 128];    // K [b][key][ch], fp16
__device__ __half g_gT[8 * 128 * 2048];         // V transposed [b][ch][key], fp16
__device__ __half g_Y[8 * 4096 * 128];          // attention out, fp16
__device__ __half g_WT[3 * 128 * 256];          // W_theta/W_g/W_phi transposed [n][k] fp16
__device__ __half g_WzT[256 * 128];             // W_z transposed [n][k] fp16

__device__ __forceinline__ float elu_f(float v) { return v > 0.f ? v : expm1f(v); }

__device__ __forceinline__ unsigned sptr(const void* p) {
    return (unsigned)__cvta_generic_to_shared(p);
}

__device__ __forceinline__ void mma16816(float* c, const unsigned* a, unsigned b0, unsigned b1) {
    asm volatile(
        "mma.sync.aligned.m16n8k16.row.col.f32.f16.f16.f32 "
        "{%0,%1,%2,%3}, {%4,%5,%6,%7}, {%8,%9}, {%0,%1,%2,%3};"
        : "+f"(c[0]), "+f"(c[1]), "+f"(c[2]), "+f"(c[3])
        : "r"(a[0]), "r"(a[1]), "r"(a[2]), "r"(a[3]), "r"(b0), "r"(b1));
}

__device__ __forceinline__ void mma16816_h(unsigned* c, const unsigned* a, unsigned b0, unsigned b1) {
    asm volatile(
        "mma.sync.aligned.m16n8k16.row.col.f16.f16.f16.f16 "
        "{%0,%1}, {%2,%3,%4,%5}, {%6,%7}, {%0,%1};"
        : "+r"(c[0]), "+r"(c[1])
        : "r"(a[0]), "r"(a[1]), "r"(a[2]), "r"(a[3]), "r"(b0), "r"(b1));
}

__device__ __forceinline__ void ldsm4(unsigned* r, unsigned addr) {
    asm volatile("ldmatrix.sync.aligned.m8n8.x4.shared.b16 {%0,%1,%2,%3}, [%4];"
                 : "=r"(r[0]), "=r"(r[1]), "=r"(r[2]), "=r"(r[3]) : "r"(addr));
}

__device__ __forceinline__ unsigned ex2h2x(unsigned x) {
    unsigned r; asm("ex2.approx.f16x2 %0, %1;" : "=r"(r) : "r"(x)); return r;
}

// ---------------- kernel 1: bn1+elu (blocks < 8192) fused with weight prep (blocks >= 8192) ----------------
__global__ void __launch_bounds__(256) k_bn1_wprep(
    const float4* __restrict__ in,
    const float* __restrict__ gamma, const float* __restrict__ beta,
    const float* __restrict__ mean, const float* __restrict__ var,
    __half* __restrict__ X,
    const float* __restrict__ Wth, const float* __restrict__ Wg, const float* __restrict__ Wph,
    const float* __restrict__ Wz, __half* __restrict__ WT, __half* __restrict__ WzT)
{
    if (blockIdx.x >= 8192) {
        int idx = (blockIdx.x - 8192) * 256 + threadIdx.x;   // 512*256 = 131072
        if (idx < 98304) {
            int m = idx >> 15;
            int r = idx & 32767;
            int n = r >> 8, k = r & 255;
            const float* W = (m == 0) ? Wth : (m == 1) ? Wg : Wph;
            WT[idx] = __float2half(W[k * 128 + n]);
        } else {
            int r = idx - 98304;
            int n = r >> 7, k = r & 127;
            WzT[r] = __float2half(Wz[k * 256 + n]);
        }
        return;
    }
    int i = blockIdx.x * 256 + threadIdx.x;
    int c = (i & 63) * 4;
    float4 v = in[i];
    float ox = elu_f(fmaf(v.x - mean[c + 0], gamma[c + 0] * rsqrtf(var[c + 0] + EPS), beta[c + 0]));
    float oy = elu_f(fmaf(v.y - mean[c + 1], gamma[c + 1] * rsqrtf(var[c + 1] + EPS), beta[c + 1]));
    float oz = elu_f(fmaf(v.z - mean[c + 2], gamma[c + 2] * rsqrtf(var[c + 2] + EPS), beta[c + 2]));
    float ow = elu_f(fmaf(v.w - mean[c + 3], gamma[c + 3] * rsqrtf(var[c + 3] + EPS), beta[c + 3]));
    __half2 h0 = __floats2half2_rn(ox, oy);
    __half2 h1 = __floats2half2_rn(oz, ow);
    uint2 u; u.x = *(unsigned*)&h0; u.y = *(unsigned*)&h1;
    *(uint2*)(X + (size_t)i * 4) = u;
}

// ---------------- kernel 2: three 1x1 convs, fp16 tensor GEMM + fused pool/transpose ----------------
#define G3_STAGE 18432   // halves per stage: As 128*72 + Ws 128*72
#define G3_SMEM (2 * G3_STAGE * 2)
__global__ void __launch_bounds__(256, 2) k_gemm3_tc(
    const __half* __restrict__ X, const __half* __restrict__ WTall,
    const float* __restrict__ b0p, const float* __restrict__ b1p, const float* __restrict__ b2p,
    __half* __restrict__ theta, __half* __restrict__ gT, __half* __restrict__ phipool)
{
    extern __shared__ __half sm[];
    const __half* WT; const float* bias;
    if (blockIdx.y == 0)      { WT = WTall;         bias = b0p; }
    else if (blockIdx.y == 1) { WT = WTall + 32768; bias = b1p; }
    else                      { WT = WTall + 65536; bias = b2p; }

    int m0 = blockIdx.x * 128;
    int tid = threadIdx.x;
    int w = tid >> 5, l = tid & 31;
    int g = l >> 2, t = l & 3;

    auto issue = [&](int stg, int kc) {
        __half* As = sm + stg * G3_STAGE;
        __half* Ws = As + 9216;
#pragma unroll
        for (int u = 0; u < 4; u++) {
            int i = tid + u * 256;
            int r = i >> 3, c8 = (i & 7) * 8;
            asm volatile("cp.async.cg.shared.global [%0], [%1], 16;\n"
                         :: "r"(sptr(As + r * 72 + c8)), "l"(X + (size_t)(m0 + r) * 256 + kc * 64 + c8));
        }
#pragma unroll
        for (int u = 0; u < 4; u++) {
            int i = tid + u * 256;
            int n = i >> 3, c8 = (i & 7) * 8;
            asm volatile("cp.async.cg.shared.global [%0], [%1], 16;\n"
                         :: "r"(sptr(Ws + n * 72 + c8)), "l"(WT + n * 256 + kc * 64 + c8));
        }
    };

    float c[16][4];
#pragma unroll
    for (int j = 0; j < 16; j++)
#pragma unroll
        for (int q = 0; q < 4; q++) c[j][q] = 0.f;

    issue(0, 0);
    asm volatile("cp.async.commit_group;\n");

    for (int kc = 0; kc < 4; ++kc) {
        int cur = kc & 1;
        asm volatile("cp.async.wait_group 0;\n");
        __syncthreads();
        if (kc < 3) {
            issue(cur ^ 1, kc + 1);
            asm volatile("cp.async.commit_group;\n");
        }
        const __half* As = sm + cur * G3_STAGE;
        const __half* Ws = As + 9216;
        int arow = w * 16 + g;
#pragma unroll
        for (int s = 0; s < 4; s++) {
            unsigned a[4];
            a[0] = *(const unsigned*)(As + arow * 72 + s * 16 + 2 * t);
            a[1] = *(const unsigned*)(As + (arow + 8) * 72 + s * 16 + 2 * t);
            a[2] = *(const unsigned*)(As + arow * 72 + s * 16 + 8 + 2 * t);
            a[3] = *(const unsigned*)(As + (arow + 8) * 72 + s * 16 + 8 + 2 * t);
#pragma unroll
            for (int j = 0; j < 16; j++) {
                unsigned bb0 = *(const unsigned*)(Ws + (8 * j + g) * 72 + s * 16 + 2 * t);
                unsigned bb1 = *(const unsigned*)(Ws + (8 * j + g) * 72 + s * 16 + 8 + 2 * t);
                mma16816(c[j], a, bb0, bb1);
            }
        }
    }

    if (blockIdx.y == 0) {
        int row = m0 + w * 16 + g;
#pragma unroll
        for (int j = 0; j < 16; j++) {
            int col = j * 8 + 2 * t;
            float bx = bias[col], by = bias[col + 1];
            *(__half2*)(theta + (size_t)row * 128 + col) = __floats2half2_rn(c[j][0] + bx, c[j][1] + by);
            *(__half2*)(theta + (size_t)(row + 8) * 128 + col) = __floats2half2_rn(c[j][2] + bx, c[j][3] + by);
        }
        return;
    }

    __syncthreads();
    __half* Cs = sm;                  // [128][136]
    int row = w * 16 + g;
#pragma unroll
    for (int j = 0; j < 16; j++) {
        int col = j * 8 + 2 * t;
        float bx = bias[col], by = bias[col + 1];
        *(__half2*)(Cs + row * 136 + col) = __floats2half2_rn(c[j][0] + bx, c[j][1] + by);
        *(__half2*)(Cs + (row + 8) * 136 + col) = __floats2half2_rn(c[j][2] + bx, c[j][3] + by);
    }
    __syncthreads();

    int bb = m0 >> 12;
    int key0 = (m0 >> 1) & 2047;

    if (blockIdx.y == 2) {
        for (int i = tid; i < 64 * 16; i += 256) {
            int r = i >> 4, c8 = (i & 15) * 8;
            uint4 a4 = *(const uint4*)(Cs + (2 * r) * 136 + c8);
            uint4 b4 = *(const uint4*)(Cs + (2 * r + 1) * 136 + c8);
            __half2* ah = (__half2*)&a4;
            __half2* bh = (__half2*)&b4;
            uint4 o;
            __half2* oh = (__half2*)&o;
#pragma unroll
            for (int k = 0; k < 4; k++) oh[k] = __hmax2(ah[k], bh[k]);
            *(uint4*)(phipool + ((size_t)bb * 2048 + key0 + r) * 128 + c8) = o;
        }
    } else {
        if (tid < 128) {
            int ch = tid;
            __half tmp[64];
#pragma unroll
            for (int k = 0; k < 64; k++)
                tmp[k] = __hmax(Cs[(2 * k) * 136 + ch], Cs[(2 * k + 1) * 136 + ch]);
            float4* dst = (float4*)(gT + ((size_t)(bb * 128 + ch)) * 2048 + key0);
            const float4* src = (const float4*)tmp;
#pragma unroll
            for (int i = 0; i < 8; i++) dst[i] = src[i];
        }
    }
}

// ---------------- kernel 3: flash attention — 8 warps x 32 query rows (Q tile = 256), R14-exact ----------------
#define STAGE_H 17920
#define KOFF 0
#define GOFF 8704
#define ATTN_SMEM (2 * STAGE_H * 2)

__device__ __forceinline__ void issue_stage(__half* sm, int stg, int kt, int tid,
                                            const __half* Kg, const __half* Gg)
{
    __half* Kd = sm + stg * STAGE_H + KOFF;
    __half* Gd = sm + stg * STAGE_H + GOFF;
    const __half* Kt = Kg + (size_t)kt * 64 * 128;
    const __half* Gt = Gg + kt * 64;
#pragma unroll
    for (int u = 0; u < 4; u++) {
        int i = tid + u * 256;
        int r = i >> 4, c8 = (i & 15) * 8;
        asm volatile("cp.async.cg.shared.global [%0], [%1], 16;\n"
                     :: "r"(sptr(Kd + r * 136 + c8)), "l"(Kt + r * 128 + c8));
    }
#pragma unroll
    for (int u = 0; u < 4; u++) {
        int i = tid + u * 256;
        int ch = i >> 3, c8 = (i & 7) * 8;
        asm volatile("cp.async.cg.shared.global [%0], [%1], 16;\n"
                     :: "r"(sptr(Gd + ch * 72 + c8)), "l"(Gt + (size_t)ch * 2048 + c8));
    }
}

__global__ void __launch_bounds__(256, 1) k_attn(
    const __half* __restrict__ theta, const __half* __restrict__ phiK,
    const __half* __restrict__ gT, __half* __restrict__ Y)
{
    extern __shared__ __half sm[];

    int b = blockIdx.y, qt = blockIdx.x;
    int tid = threadIdx.x;
    int w = tid >> 5, l = tid & 31;
    int g = l >> 2, t = l & 3;
    const float L2E = 1.4426950408889634f;
    const __half2 L2E2 = __float2half2_rn(L2E);

    int lrowB = (l & 7) + ((l >> 4) << 3);
    int lcolB = ((l >> 3) & 1) * 8;
    int lrowA = (l & 7) + (((l >> 3) & 1) << 3);
    int lcolA = (l >> 4) * 8;

    const __half* Qg = theta + ((size_t)b * 4096 + qt * 256) * 128;
    for (int i = tid; i < 256 * 16; i += 256) {
        int r = i >> 4, c8 = (i & 15) * 8;
        *(float4*)(sm + r * 136 + c8) = *(const float4*)(Qg + r * 128 + c8);
    }
    __syncthreads();

    unsigned a_q[2][8][4];
#pragma unroll
    for (int mt = 0; mt < 2; mt++)
#pragma unroll
        for (int s = 0; s < 8; s++)
            ldsm4(a_q[mt][s], sptr(sm + (w * 32 + mt * 16 + lrowA) * 136 + s * 16 + lcolA));
    __syncthreads();

    const __half* Kg = phiK + (size_t)b * 2048 * 128;
    const __half* Gg = gT + (size_t)b * 128 * 2048;

    unsigned oh[2][16][2];
#pragma unroll
    for (int mt = 0; mt < 2; mt++)
#pragma unroll
        for (int j = 0; j < 16; j++) { oh[mt][j][0] = 0u; oh[mt][j][1] = 0u; }
    float mreg[2][2] = {{-1e30f, -1e30f}, {-1e30f, -1e30f}};
    float lreg[2][2] = {{0.f, 0.f}, {0.f, 0.f}};

    issue_stage(sm, 0, 0, tid, Kg, Gg);
    asm volatile("cp.async.commit_group;\n");

    for (int kt = 0; kt < 32; ++kt) {
        int cur = kt & 1;
        asm volatile("cp.async.wait_group 0;\n");
        __syncthreads();
        if (kt < 31) {
            issue_stage(sm, cur ^ 1, kt + 1, tid, Kg, Gg);
            asm volatile("cp.async.commit_group;\n");
        }

        const __half* Ks = sm + cur * STAGE_H + KOFF;
        const __half* Gs = sm + cur * STAGE_H + GOFF;

        unsigned ch2[2][8][2];
#pragma unroll
        for (int mt = 0; mt < 2; mt++)
#pragma unroll
            for (int j = 0; j < 8; j++) { ch2[mt][j][0] = 0u; ch2[mt][j][1] = 0u; }
#pragma unroll
        for (int s = 0; s < 8; s++) {
#pragma unroll
            for (int jp = 0; jp < 4; jp++) {
                unsigned bm[4];
                ldsm4(bm, sptr(Ks + (16 * jp + lrowB) * 136 + s * 16 + lcolB));
#pragma unroll
                for (int mt = 0; mt < 2; mt++) {
                    mma16816_h(ch2[mt][2 * jp], a_q[mt][s], bm[0], bm[1]);
                    mma16816_h(ch2[mt][2 * jp + 1], a_q[mt][s], bm[2], bm[3]);
                }
            }
        }

        unsigned P0[2][8], P1[2][8];
        __half2 alh[2][2];
#pragma unroll
        for (int mt = 0; mt < 2; mt++) {
            __half2 hm0 = *(__half2*)&ch2[mt][0][0], hm1 = *(__half2*)&ch2[mt][0][1];
#pragma unroll
            for (int j = 1; j < 8; j++) {
                hm0 = __hmax2(hm0, *(__half2*)&ch2[mt][j][0]);
                hm1 = __hmax2(hm1, *(__half2*)&ch2[mt][j][1]);
            }
            float rmax0 = fmaxf(__low2float(hm0), __high2float(hm0));
            float rmax1 = fmaxf(__low2float(hm1), __high2float(hm1));
            rmax0 = fmaxf(rmax0, __shfl_xor_sync(0xffffffffu, rmax0, 1));
            rmax0 = fmaxf(rmax0, __shfl_xor_sync(0xffffffffu, rmax0, 2));
            rmax1 = fmaxf(rmax1, __shfl_xor_sync(0xffffffffu, rmax1, 1));
            rmax1 = fmaxf(rmax1, __shfl_xor_sync(0xffffffffu, rmax1, 2));
            float mn0 = fmaxf(mreg[mt][0], rmax0), mn1 = fmaxf(mreg[mt][1], rmax1);
            float al0 = __expf(mreg[mt][0] - mn0), al1 = __expf(mreg[mt][1] - mn1);
            mreg[mt][0] = mn0; mreg[mt][1] = mn1;
            __half2 nb0 = __float2half2_rn(-mn0 * L2E);
            __half2 nb1 = __float2half2_rn(-mn1 * L2E);

            float s0 = 0.f, s1 = 0.f;
#pragma unroll
            for (int j = 0; j < 8; j++) {
                __half2 d0 = __hfma2(*(__half2*)&ch2[mt][j][0], L2E2, nb0);
                __half2 d1 = __hfma2(*(__half2*)&ch2[mt][j][1], L2E2, nb1);
                P0[mt][j] = ex2h2x(*(unsigned*)&d0);
                P1[mt][j] = ex2h2x(*(unsigned*)&d1);
                float2 f0 = __half22float2(*(__half2*)&P0[mt][j]);
                float2 f1 = __half22float2(*(__half2*)&P1[mt][j]);
                s0 += f0.x + f0.y;
                s1 += f1.x + f1.y;
            }
            s0 += __shfl_xor_sync(0xffffffffu, s0, 1);
            s0 += __shfl_xor_sync(0xffffffffu, s0, 2);
            s1 += __shfl_xor_sync(0xffffffffu, s1, 1);
            s1 += __shfl_xor_sync(0xffffffffu, s1, 2);
            lreg[mt][0] = lreg[mt][0] * al0 + s0;
            lreg[mt][1] = lreg[mt][1] * al1 + s1;
            alh[mt][0] = __float2half2_rn(al0);
            alh[mt][1] = __float2half2_rn(al1);
        }
#pragma unroll
        for (int mt = 0; mt < 2; mt++)
#pragma unroll
            for (int j = 0; j < 16; j++) {
                *(__half2*)&oh[mt][j][0] = __hmul2(*(__half2*)&oh[mt][j][0], alh[mt][0]);
                *(__half2*)&oh[mt][j][1] = __hmul2(*(__half2*)&oh[mt][j][1], alh[mt][1]);
            }

#pragma unroll
        for (int s = 0; s < 4; s++) {
            unsigned pa[2][4];
#pragma unroll
            for (int mt = 0; mt < 2; mt++) {
                pa[mt][0] = P0[mt][2 * s]; pa[mt][1] = P1[mt][2 * s];
                pa[mt][2] = P0[mt][2 * s + 1]; pa[mt][3] = P1[mt][2 * s + 1];
            }
#pragma unroll
            for (int jp = 0; jp < 8; jp++) {
                unsigned gm[4];
                ldsm4(gm, sptr(Gs + (16 * jp + lrowB) * 72 + s * 16 + lcolB));
#pragma unroll
                for (int mt = 0; mt < 2; mt++) {
                    mma16816_h(oh[mt][2 * jp], pa[mt], gm[0], gm[1]);
                    mma16816_h(oh[mt][2 * jp + 1], pa[mt], gm[2], gm[3]);
                }
            }
        }
    }

#pragma unroll
    for (int mt = 0; mt < 2; mt++) {
        float inv0 = 1.f / lreg[mt][0], inv1 = 1.f / lreg[mt][1];
        __half2 i0 = __float2half2_rn(inv0), i1 = __float2half2_rn(inv1);
        size_t base = (size_t)b * 4096 + qt * 256 + w * 32 + mt * 16;
#pragma unroll
        for (int j = 0; j < 16; j++) {
            __half2 v0 = __hmul2(*(__half2*)&oh[mt][j][0], i0);
            __half2 v1 = __hmul2(*(__half2*)&oh[mt][j][1], i1);
            *(__half2*)(Y + (base + g) * 128 + j * 8 + 2 * t) = v0;
            *(__half2*)(Y + (base + g + 8) * 128 + j * 8 + 2 * t) = v1;
        }
    }
}

// ---------------- kernel 4: out = elu(bn2(Y)) @ W_z + b_z, *sita + inputs (R14-exact) ----------------
#define GZ_SMEM (1024 + 2 * 128 * 136 * 2)
__global__ void __launch_bounds__(256, 2) k_gemm_z_tc(
    const __half* __restrict__ Yh, const __half* __restrict__ WzT,
    const float* __restrict__ bz,
    const float* __restrict__ g2, const float* __restrict__ b2,
    const float* __restrict__ m2, const float* __restrict__ v2,
    const float* __restrict__ sita, const float* __restrict__ resid, float* __restrict__ out)
{
    extern __shared__ char smz[];
    float* bnS = (float*)smz;
    float* bnH = bnS + 128;
    __half* As = (__half*)(bnH + 128);
    __half* Ws = As + 128 * 136;
    float* Cs = (float*)As;                 // fp32 staging [128][132], reuses As/Ws after mma

    int m0 = blockIdx.x * 128;
    int n0 = blockIdx.y * 128;
    int tid = threadIdx.x;
    int w = tid >> 5, l = tid & 31;
    int g = l >> 2, t = l & 3;

    if (tid < 128) {
        float s = g2[tid] * rsqrtf(v2[tid] + EPS);
        bnS[tid] = s;
        bnH[tid] = b2[tid] - m2[tid] * s;
    }
    __syncthreads();

    for (int i = tid; i < 128 * 16; i += 256) {
        int r = i >> 4, c8 = (i & 15) * 8;
        uint4 u = *(const uint4*)(Yh + (size_t)(m0 + r) * 128 + c8);
        __half2* hp = (__half2*)&u;
        uint4 o;
        __half2* op = (__half2*)&o;
#pragma unroll
        for (int k = 0; k < 4; k++) {
            float2 f = __half22float2(hp[k]);
            int c = c8 + 2 * k;
            f.x = elu_f(fmaf(f.x, bnS[c], bnH[c]));
            f.y = elu_f(fmaf(f.y, bnS[c + 1], bnH[c + 1]));
            op[k] = __floats2half2_rn(f.x, f.y);
        }
        *(uint4*)(As + r * 136 + c8) = o;
    }
    for (int i = tid; i < 128 * 16; i += 256) {
        int n = i >> 4, c8 = (i & 15) * 8;
        *(uint4*)(Ws + n * 136 + c8) = *(const uint4*)(WzT + (size_t)(n0 + n) * 128 + c8);
    }
    __syncthreads();

    float c[16][4];
#pragma unroll
    for (int j = 0; j < 16; j++)
#pragma unroll
        for (int q = 0; q < 4; q++) c[j][q] = 0.f;

    int arow = w * 16 + g;
#pragma unroll
    for (int s = 0; s < 8; s++) {
        unsigned a[4];
        a[0] = *(const unsigned*)(As + arow * 136 + s * 16 + 2 * t);
        a[1] = *(const unsigned*)(As + (arow + 8) * 136 + s * 16 + 2 * t);
        a[2] = *(const unsigned*)(As + arow * 136 + s * 16 + 8 + 2 * t);
        a[3] = *(const unsigned*)(As + (arow + 8) * 136 + s * 16 + 8 + 2 * t);
#pragma unroll
        for (int j = 0; j < 16; j++) {
            unsigned bb0 = *(const unsigned*)(Ws + (8 * j + g) * 136 + s * 16 + 2 * t);
            unsigned bb1 = *(const unsigned*)(Ws + (8 * j + g) * 136 + s * 16 + 8 + 2 * t);
            mma16816(c[j], a, bb0, bb1);
        }
    }

    // stage accumulators into fp32 smem tile (As/Ws region is dead after mma)
    __syncthreads();
#pragma unroll
    for (int j = 0; j < 16; j++) {
        int col = j * 8 + 2 * t;
        *(float2*)(Cs + arow * 132 + col) = make_float2(c[j][0], c[j][1]);
        *(float2*)(Cs + (arow + 8) * 132 + col) = make_float2(c[j][2], c[j][3]);
    }
    __syncthreads();

    // coalesced epilogue: float4 everywhere
    float st = *sita;
#pragma unroll
    for (int u = 0; u < 16; u++) {
        int i = tid + u * 256;               // [0, 4096)
        int r = i >> 5, c4 = (i & 31) * 4;
        float4 cv = *(const float4*)(Cs + r * 132 + c4);
        float4 bv = *(const float4*)(bz + n0 + c4);
        float4 rv = *(const float4*)(resid + (size_t)(m0 + r) * 256 + n0 + c4);
        float4 ov;
        ov.x = fmaf(cv.x + bv.x, st, rv.x);
        ov.y = fmaf(cv.y + bv.y, st, rv.y);
        ov.z = fmaf(cv.z + bv.z, st, rv.z);
        ov.w = fmaf(cv.w + bv.w, st, rv.w);
        *(float4*)(out + (size_t)(m0 + r) * 256 + n0 + c4) = ov;
    }
}

// ---------------- launcher ----------------
extern "C" void kernel_launch(void* const* d_in, const int* in_sizes, int n_in,
                              void* d_out, int out_size)
{
    const float* inputs = (const float*)d_in[0];
    const float* bn1g = (const float*)d_in[1];
    const float* bn1b = (const float*)d_in[2];
    const float* bn1m = (const float*)d_in[3];
    const float* bn1v = (const float*)d_in[4];
    const float* bn2g = (const float*)d_in[5];
    const float* bn2b = (const float*)d_in[6];
    const float* bn2m = (const float*)d_in[7];
    const float* bn2v = (const float*)d_in[8];
    const float* Wg   = (const float*)d_in[9];
    const float* bg   = (const float*)d_in[10];
    const float* Wth  = (const float*)d_in[11];
    const float* bth  = (const float*)d_in[12];
    const float* Wph  = (const float*)d_in[13];
    const float* bph  = (const float*)d_in[14];
    const float* Wz   = (const float*)d_in[15];
    const float* bz   = (const float*)d_in[16];
    const float* sita = (const float*)d_in[17];
    float* out = (float*)d_out;

    __half *X, *theta, *phipool, *gT, *Y, *WT, *WzT;
    cudaGetSymbolAddress((void**)&X, g_X);
    cudaGetSymbolAddress((void**)&theta, g_theta);
    cudaGetSymbolAddress((void**)&phipool, g_phipool);
    cudaGetSymbolAddress((void**)&gT, g_gT);
    cudaGetSymbolAddress((void**)&Y, g_Y);
    cudaGetSymbolAddress((void**)&WT, g_WT);
    cudaGetSymbolAddress((void**)&WzT, g_WzT);

    cudaFuncSetAttribute(k_attn, cudaFuncAttributeMaxDynamicSharedMemorySize, ATTN_SMEM);
    cudaFuncSetAttribute(k_gemm3_tc, cudaFuncAttributeMaxDynamicSharedMemorySize, G3_SMEM);
    cudaFuncSetAttribute(k_gemm_z_tc, cudaFuncAttributeMaxDynamicSharedMemorySize, GZ_SMEM);

    // 1) bn1 + elu (fp16 out) fused with weight prep
    k_bn1_wprep<<<8704, 256>>>((const float4*)inputs, bn1g, bn1b, bn1m, bn1v, X,
                               Wth, Wg, Wph, Wz, WT, WzT);
    // 2) theta / g / phi convs (tensor core) with fused pool+transpose for g/phi
    k_gemm3_tc<<<dim3(256, 3), 256, G3_SMEM>>>(X, WT, bth, bg, bph, theta, gT, phipool);
    // 3) flash attention (8 warps x 32 rows, Q tile 256, 2-stage)
    k_attn<<<dim3(16, 8), 256, ATTN_SMEM>>>(theta, phipool, gT, Y);
    // 4) bn2+elu -> W_z -> *sita + residual (tensor core, coalesced epilogue)
    k_gemm_z_tc<<<dim3(256, 2), 256, GZ_SMEM>>>(Y, WzT, bz, bn2g, bn2b, bn2m, bn2v, sita, inputs, out);
}